// round 10
// baseline (speedup 1.0000x reference)
#include <cuda_runtime.h>
#include <cuda_bf16.h>

#define BB 8
#define NN 2048
#define BIGF 1e30f

// z-bucketing
#define NB   64
#define ZLO  (-6.0f)
#define ZHI  (6.0f)
#define ZW   ((ZHI - ZLO) / NB)
#define ZINV (NB / (ZHI - ZLO))

// main kernel shape: warp = 16 queries x 2 lanes; block = 4 warps = 64 queries
#define W0    0.75f
#define QPW   16
#define QPB   64
#define CHQ   (NN / QPB)          // 32 query chunks
#define GZT   16                  // tasks (dir, b)
#define NBLK  (CHQ * GZT)         // 512 blocks
#define NCHNK (NN / QPW)          // 128 warp-chunks per task

// Scratch (allocation-free). Points transformed: (x+y, x-y, z, 0), z-sorted.
// g_valid[0]=clean(points+target), g_valid[1]=predp(points+pred)
__device__ __align__(16) float4 g_valid[2][BB][NN];
__device__ int          g_S[2][BB][NB + 1];   // bucket starts, S[NB]=cnt
__device__ int          g_cnt[BB];
__device__ float        g_l1part[BB];
__device__ float        g_warpsum[GZT][NCHNK];
__device__ unsigned int g_done;               // zero at load; reset by last block

// ---------------------------------------------------------------------------
// Kernel 1: prep — 16 blocks (set s, batch b) x 1024 threads, 2 points/thread.
// Counting-sort valid points into z-buckets; l1 partial (s==0 only).
// ---------------------------------------------------------------------------
__global__ void __launch_bounds__(1024)
prep_kernel(const float* __restrict__ pred,
            const float* __restrict__ target,
            const int*   __restrict__ mask,
            const float* __restrict__ points) {
    int s = blockIdx.x & 1, b = blockIdx.x >> 1;
    int tid = threadIdx.x;

    __shared__ int   hist[NB];
    __shared__ int   bstart[NB + 1];
    __shared__ int   cursor[NB];
    __shared__ float wred[32];

    if (tid < NB) hist[tid] = 0;
    __syncthreads();

    float u[2], v[2], z[2];
    int   valid[2], bk[2];
    float l1 = 0.f;
#pragma unroll
    for (int it = 0; it < 2; ++it) {
        int n  = tid + it * 1024;
        int gi = b * NN + n;
        const float* xx = points + gi * 3;
        const float* aa = (s ? pred : target) + gi * 3;
        float a0 = aa[0], a1 = aa[1], a2 = aa[2];
        float x0 = xx[0], x1 = xx[1], x2 = xx[2];
        valid[it] = mask[gi];
        float P0 = x0 + a0, P1 = x1 + a1, P2 = x2 + a2;
        u[it] = P0 + P1; v[it] = P0 - P1; z[it] = P2;
        bk[it] = 0;
        if (valid[it]) {
            int k = (int)floorf((P2 - ZLO) * ZINV);
            k = max(0, min(NB - 1, k));
            bk[it] = k;
            atomicAdd(&hist[k], 1);
            if (s == 0) {
                const float* pp = pred + gi * 3;
                l1 += fabsf(pp[0] - a0) + fabsf(pp[1] - a1) + fabsf(pp[2] - a2);
            }
        }
    }
    __syncthreads();

    if (tid == 0) {
        int acc = 0;
#pragma unroll
        for (int k = 0; k < NB; ++k) { bstart[k] = acc; acc += hist[k]; }
        bstart[NB] = acc;
    }
    __syncthreads();
    if (tid < NB)  cursor[tid] = bstart[tid];
    if (tid <= NB) g_S[s][b][tid] = bstart[tid];
    if (s == 0 && tid == 0) g_cnt[b] = bstart[NB];
    __syncthreads();

#pragma unroll
    for (int it = 0; it < 2; ++it)
        if (valid[it]) {
            int pos = atomicAdd(&cursor[bk[it]], 1);
            g_valid[s][b][pos] = make_float4(u[it], v[it], z[it], 0.f);
        }

    if (s == 0) {
#pragma unroll
        for (int o = 16; o > 0; o >>= 1) l1 += __shfl_xor_sync(0xffffffffu, l1, o);
        if ((tid & 31) == 0) wred[tid >> 5] = l1;
        __syncthreads();
        if (tid == 0) {
            float t = 0.f;
#pragma unroll
            for (int i = 0; i < 32; ++i) t += wred[i];
            g_l1part[b] = t;
        }
    }
}

// ---------------------------------------------------------------------------
// Per-lane ref scan, unroll 4, dual accumulators.
// |dx|+|dy|+|dz| == max(|du|,|dv|) + |dz| with (u,v) = (x+y, x-y).
// ---------------------------------------------------------------------------
__device__ __forceinline__ float scan_range(const float4* __restrict__ R,
                                            int j0, int j1,
                                            float qx, float qy, float qz) {
    float mn0 = BIGF, mn1 = BIGF;
    int j = j0;
    for (; j + 4 <= j1; j += 4) {
        float4 y0 = R[j+0], y1 = R[j+1], y2 = R[j+2], y3 = R[j+3];
        float d0 = fmaxf(fabsf(qx-y0.x), fabsf(qy-y0.y)) + fabsf(qz-y0.z);
        float d1 = fmaxf(fabsf(qx-y1.x), fabsf(qy-y1.y)) + fabsf(qz-y1.z);
        float d2 = fmaxf(fabsf(qx-y2.x), fabsf(qy-y2.y)) + fabsf(qz-y2.z);
        float d3 = fmaxf(fabsf(qx-y3.x), fabsf(qy-y3.y)) + fabsf(qz-y3.z);
        mn0 = fminf(mn0, fminf(d0, d1));
        mn1 = fminf(mn1, fminf(d2, d3));
    }
    for (; j < j1; ++j) {
        float4 y = R[j];
        mn0 = fminf(mn0, fmaxf(fabsf(qx-y.x), fabsf(qy-y.y)) + fabsf(qz-y.z));
    }
    return fminf(mn0, mn1);
}

// ---------------------------------------------------------------------------
// Kernel 2: validated-window chamfer. Warp = 16 queries x 2 lanes.
// Window [qz-W0, qz+W0] via buckets; post-validate with true bucket-edge
// margin M; rare failures rescan the full range inline (exact by construction).
// ---------------------------------------------------------------------------
__global__ void __launch_bounds__(128)
chamfer_kernel(float* __restrict__ out) {
    int task = blockIdx.y;
    int b    = task >> 1;
    int dir  = task & 1;                 // 0: clean->pred, 1: pred->clean
    int cnt  = g_cnt[b];
    int tid  = threadIdx.x;
    int w    = tid >> 5, lane = tid & 31;
    int half = lane & 1;
    int chunk = blockIdx.x * 4 + w;      // 0..127
    int qidx  = chunk * QPW + (lane >> 1);
    bool active = qidx < cnt;

    float warpsum = 0.f;
    if (chunk * QPW < cnt) {             // warp has work
        const float4* __restrict__ Q = g_valid[dir][b];
        const float4* __restrict__ R = g_valid[dir ^ 1][b];
        const int*    __restrict__ S = g_S[dir ^ 1][b];

        float4 vq = Q[active ? qidx : 0];
        float qx = vq.x, qy = vq.y, qz = vq.z;

        int klo = max(0, min(NB - 1, (int)floorf((qz - W0 - ZLO) * ZINV)));
        int khi = max(0, min(NB - 1, (int)floorf((qz + W0 - ZLO) * ZINV)));
        int j0 = S[klo], j1 = S[khi + 1];
        int jm = (j0 + j1) >> 1;
        int lo = half ? jm : j0;
        int hi = half ? j1 : jm;

        float mn = scan_range(R, lo, hi, qx, qy, qz);
        float m  = fminf(mn, __shfl_xor_sync(0xffffffffu, mn, 1));

        // guaranteed exclusion margin from actual bucket edges
        float zBlo = ZLO + klo * ZW;
        float zBhi = ZLO + (khi + 1) * ZW;
        float Ml = (klo > 0)      ? (qz - zBlo) : BIGF;
        float Mh = (khi < NB - 1) ? (zBhi - qz) : BIGF;
        float M  = fminf(Ml, Mh);

        bool fail = active && (m > M - 1e-5f);
        unsigned fmask = __ballot_sync(0xffffffffu, fail);
        if (fmask) {
            if (fail) {                  // both lanes of a query fail together
                int fm = cnt >> 1;
                float mnf = scan_range(R, half ? fm : 0, half ? cnt : fm,
                                       qx, qy, qz);
                m = fminf(mnf, __shfl_xor_sync(fmask, mnf, 1));
            }
        }
        __syncwarp();

        float sv = (active && half == 0) ? m : 0.f;   // count each query once
#pragma unroll
        for (int o = 16; o > 0; o >>= 1) sv += __shfl_xor_sync(0xffffffffu, sv, o);
        warpsum = sv;
    }
    if (lane == 0) g_warpsum[task][chunk] = warpsum;

    // -------- arrive; last block finalizes --------
    __threadfence();
    __syncthreads();
    __shared__ int is_last;
    if (tid == 0)
        is_last = (atomicAdd(&g_done, 1u) == NBLK - 1);
    __syncthreads();
    if (!is_last) return;
    __threadfence();

    // finalize: 128 threads; thread tid owns slot tid across all 16 tasks
    float acc = 0.f;
#pragma unroll
    for (int t = 0; t < GZT; ++t)
        acc += g_warpsum[t][tid] / (float)g_cnt[t >> 1];

    __shared__ float wa[4];
#pragma unroll
    for (int o = 16; o > 0; o >>= 1) acc += __shfl_xor_sync(0xffffffffu, acc, o);
    if ((tid & 31) == 0) wa[tid >> 5] = acc;
    __syncthreads();
    if (tid == 0) {
        float cdsum = wa[0] + wa[1] + wa[2] + wa[3];
        float l1num = 0.f; int msum = 0;
#pragma unroll
        for (int bb = 0; bb < BB; ++bb) { l1num += g_l1part[bb]; msum += g_cnt[bb]; }
        float l1 = l1num / 3.0f / (float)msum;
        float cd = cdsum / (float)BB;
        out[0] = l1 + expf(-l1) * cd;
        g_done = 0;                      // reset for next graph replay
    }
}

// ---------------------------------------------------------------------------
extern "C" void kernel_launch(void* const* d_in, const int* in_sizes, int n_in,
                              void* d_out, int out_size) {
    const float* pred   = (const float*)d_in[0];
    const float* target = (const float*)d_in[1];
    const int*   mask   = (const int*)  d_in[2];
    const float* points = (const float*)d_in[3];
    float* out = (float*)d_out;

    prep_kernel<<<16, 1024>>>(pred, target, mask, points);

    dim3 grid(CHQ, GZT);                 // (32, 16) = 512 blocks
    chamfer_kernel<<<grid, 128>>>(out);
}

// round 11
// speedup vs baseline: 2.6090x; 2.6090x over previous
#include <cuda_runtime.h>
#include <cuda_bf16.h>

#define BB 8
#define NN 2048
#define BIGF 1e30f

// chamfer shape: all chunks cnt-relative -> zero dead blocks
#define TB     128
#define GQ     4                 // query chunks (passes inside block)
#define RSPLIT 32                // ref chunks
#define RTILE  64                // max rlen = ceil(2048/32)
#define GZ     (2 * BB)          // 16 tasks
#define ARR_PER_TASK (GQ * RSPLIT)   // 128 arrivals per task

// Scratch (allocation-free). Points transformed: (x+y, x-y, z, 0).
// g_valid[0]=clean(points+target), g_valid[1]=predp(points+pred)
__device__ __align__(16) float4       g_valid[2][BB][NN];
__device__ __align__(16) unsigned int g_minbits[2][BB][NN];
__device__ int          g_cnt[BB];          // zero at load; reset by last block
__device__ float        g_l1part[128];
__device__ float        g_tasksum[GZ];
__device__ unsigned int g_done_task[GZ];
__device__ unsigned int g_done;

// ---------------------------------------------------------------------------
// Kernel 1: prep — 128 blocks x 128 threads, one point per thread (R7 exact).
// ---------------------------------------------------------------------------
__global__ void __launch_bounds__(128)
prep_kernel(const float* __restrict__ pred,
            const float* __restrict__ target,
            const int*   __restrict__ mask,
            const float* __restrict__ points) {
    int bid = blockIdx.x, tid = threadIdx.x;
    int b = bid >> 4, s = bid & 15;
    int n  = s * 128 + tid;
    int gi = b * NN + n;

    const float* pp = pred   + gi * 3;
    const float* tt = target + gi * 3;
    const float* xx = points + gi * 3;
    float p0 = pp[0], p1 = pp[1], p2 = pp[2];
    float t0 = tt[0], t1 = tt[1], t2 = tt[2];
    float x0 = xx[0], x1 = xx[1], x2 = xx[2];
    int m = mask[gi];

    const unsigned bigbits = __float_as_uint(BIGF);
    g_minbits[0][b][n] = bigbits;
    g_minbits[1][b][n] = bigbits;

    float c0 = x0 + t0, c1 = x1 + t1, c2 = x2 + t2;   // clean
    float q0 = x0 + p0, q1 = x1 + p1, q2 = x2 + p2;   // predp
    float l1 = 0.f;

    __shared__ int sh_cnt, sh_base;
    if (tid == 0) sh_cnt = 0;
    __syncthreads();
    int klocal = -1;
    if (m) {
        l1 = fabsf(p0 - t0) + fabsf(p1 - t1) + fabsf(p2 - t2);
        klocal = atomicAdd(&sh_cnt, 1);
    }
    __syncthreads();
    if (tid == 0) sh_base = atomicAdd(&g_cnt[b], sh_cnt);

    __shared__ float wsum[4];
#pragma unroll
    for (int o = 16; o > 0; o >>= 1) l1 += __shfl_down_sync(0xffffffffu, l1, o);
    if ((tid & 31) == 0) wsum[tid >> 5] = l1;
    __syncthreads();
    if (tid == 0)
        g_l1part[bid] = wsum[0] + wsum[1] + wsum[2] + wsum[3];

    if (m) {
        int k = sh_base + klocal;
        g_valid[0][b][k] = make_float4(c0 + c1, c0 - c1, c2, 0.f);
        g_valid[1][b][k] = make_float4(q0 + q1, q0 - q1, q2, 0.f);
    }
}

// ---------------------------------------------------------------------------
// Kernel 2: chamfer, grid (GQ, RSPLIT, GZ) = (4, 32, 16) = 2048 blocks, TB=128.
// Both q- and r-chunks are cnt-relative: every block does real work.
// |dx|+|dy|+|dz| == max(|du|,|dv|) + |dz| with (u,v) = (x+y, x-y).
// ---------------------------------------------------------------------------
__global__ void __launch_bounds__(TB)
chamfer_kernel(float* __restrict__ out) {
    int tid  = threadIdx.x;
    int task = blockIdx.z;
    int b    = task >> 1;
    int dir  = task & 1;               // 0: clean->pred, 1: pred->clean
    int cnt  = g_cnt[b];

    __shared__ float4 tile[RTILE];
    int qn   = (cnt + GQ - 1) / GQ;            // <= 512
    int q_lo = blockIdx.x * qn;
    int q_hi = min(q_lo + qn, cnt);
    int rn   = (cnt + RSPLIT - 1) / RSPLIT;    // <= 64
    int r_lo = blockIdx.y * rn;
    int rlen = min(rn, cnt - r_lo);

    if (q_lo < cnt && rlen > 0) {
        const float4* __restrict__ Q = g_valid[dir][b];
        const float4* __restrict__ R = g_valid[dir ^ 1][b];
        unsigned int* __restrict__ M = g_minbits[dir][b];

        if (tid < RTILE)
            tile[tid] = (tid < rlen) ? R[r_lo + tid]
                                     : make_float4(BIGF, BIGF, BIGF, 0.f);
        __syncthreads();

        for (int q = q_lo + tid; q < q_hi; q += TB) {      // ~2 passes typ.
            float4 v = Q[q];
            float qx = v.x, qy = v.y, qz = v.z;
            float mn0 = BIGF, mn1 = BIGF;
            int j = 0;
            for (; j + 8 <= rlen; j += 8) {
                float4 y0 = tile[j+0], y1 = tile[j+1], y2 = tile[j+2], y3 = tile[j+3];
                float4 y4 = tile[j+4], y5 = tile[j+5], y6 = tile[j+6], y7 = tile[j+7];
                float d0 = fmaxf(fabsf(qx-y0.x), fabsf(qy-y0.y)) + fabsf(qz-y0.z);
                float d1 = fmaxf(fabsf(qx-y1.x), fabsf(qy-y1.y)) + fabsf(qz-y1.z);
                float d2 = fmaxf(fabsf(qx-y2.x), fabsf(qy-y2.y)) + fabsf(qz-y2.z);
                float d3 = fmaxf(fabsf(qx-y3.x), fabsf(qy-y3.y)) + fabsf(qz-y3.z);
                float d4 = fmaxf(fabsf(qx-y4.x), fabsf(qy-y4.y)) + fabsf(qz-y4.z);
                float d5 = fmaxf(fabsf(qx-y5.x), fabsf(qy-y5.y)) + fabsf(qz-y5.z);
                float d6 = fmaxf(fabsf(qx-y6.x), fabsf(qy-y6.y)) + fabsf(qz-y6.z);
                float d7 = fmaxf(fabsf(qx-y7.x), fabsf(qy-y7.y)) + fabsf(qz-y7.z);
                mn0 = fminf(mn0, fminf(fminf(d0, d2), fminf(d4, d6)));
                mn1 = fminf(mn1, fminf(fminf(d1, d3), fminf(d5, d7)));
            }
            for (; j < rlen; ++j) {
                float4 y = tile[j];
                mn0 = fminf(mn0, fmaxf(fabsf(qx-y.x), fabsf(qy-y.y)) + fabsf(qz-y.z));
            }
            atomicMin(&M[q], __float_as_uint(fminf(mn0, mn1)));
        }
    }

    // -------- hierarchical arrive --------
    __threadfence();
    __syncthreads();
    __shared__ int task_last;
    if (tid == 0)
        task_last = (atomicAdd(&g_done_task[task], 1u) == ARR_PER_TASK - 1);
    __syncthreads();
    if (!task_last) return;

    // -------- per-task tail: reduce this (dir,b) min array to one scalar ----
    __threadfence();
    {
        const uint4* __restrict__ p = (const uint4*)g_minbits[dir][b];
        int nv = cnt >> 2;
        float s = 0.f;
        for (int k = tid; k < nv; k += TB) {
            uint4 u = p[k];
            s += (__uint_as_float(u.x) + __uint_as_float(u.y))
               + (__uint_as_float(u.z) + __uint_as_float(u.w));
        }
        if (tid < (cnt & 3))
            s += __uint_as_float(g_minbits[dir][b][(cnt & ~3) + tid]);

        __shared__ float wsum[4];
#pragma unroll
        for (int o = 16; o > 0; o >>= 1) s += __shfl_down_sync(0xffffffffu, s, o);
        if ((tid & 31) == 0) wsum[tid >> 5] = s;
        __syncthreads();
        if (tid == 0)
            g_tasksum[task] = wsum[0] + wsum[1] + wsum[2] + wsum[3];
    }

    // -------- global arrive; last task-block combines --------
    __threadfence();
    __syncthreads();
    __shared__ int is_last;
    if (tid == 0)
        is_last = (atomicAdd(&g_done, 1u) == GZ - 1);
    __syncthreads();
    if (!is_last) return;

    __threadfence();
    float l1p = g_l1part[tid];             // 128 partials, TB == 128
    __shared__ float wl[4];
#pragma unroll
    for (int o = 16; o > 0; o >>= 1) l1p += __shfl_down_sync(0xffffffffu, l1p, o);
    if ((tid & 31) == 0) wl[tid >> 5] = l1p;
    __syncthreads();
    if (tid == 0) {
        float cdsum = 0.f;
#pragma unroll
        for (int t = 0; t < GZ; ++t)
            cdsum += g_tasksum[t] / (float)g_cnt[t >> 1];
        float l1num = wl[0] + wl[1] + wl[2] + wl[3];
        int msum = 0;
#pragma unroll
        for (int bb = 0; bb < BB; ++bb) msum += g_cnt[bb];
        float l1 = l1num / 3.0f / (float)msum;
        float cd = cdsum / (float)BB;
        out[0] = l1 + expf(-l1) * cd;
        g_done = 0;                        // reset for next graph replay
    }
    __syncthreads();
    if (tid < BB)  g_cnt[tid] = 0;
    if (tid < GZ)  g_done_task[tid] = 0;
}

// ---------------------------------------------------------------------------
extern "C" void kernel_launch(void* const* d_in, const int* in_sizes, int n_in,
                              void* d_out, int out_size) {
    const float* pred   = (const float*)d_in[0];
    const float* target = (const float*)d_in[1];
    const int*   mask   = (const int*)  d_in[2];
    const float* points = (const float*)d_in[3];
    float* out = (float*)d_out;

    prep_kernel<<<128, 128>>>(pred, target, mask, points);

    dim3 grid(GQ, RSPLIT, GZ);   // (4, 32, 16) = 2048 blocks, all live
    chamfer_kernel<<<grid, TB>>>(out);
}